// round 16
// baseline (speedup 1.0000x reference)
#include <cuda_runtime.h>
#include <cuda_bf16.h>
#include <mma.h>
#include <math.h>

using namespace nvcuda;

typedef unsigned long long ull;
typedef unsigned int u32;

#define Cc 128
#define Hd 128
#define Wd 128
#define HWs 16384
#define BT 16
#define NBm 2

// ---------------- device scratch ----------------
__device__ float g_qw[(size_t)2 * 8388608];
__device__ float g_kw[(size_t)2 * 8388608];
__device__ float g_vw[(size_t)2 * 8388608];
__device__ float g_ow[(size_t)4 * 8388608];
__device__ float g_part[(size_t)1 << 24];
__device__ float g_attn[(size_t)NBm * 512 * 512];
__device__ __nv_bfloat16 g_ath[(size_t)NBm * 512 * 512];
__device__ __nv_bfloat16 g_atl[(size_t)NBm * 512 * 512];
__device__ __nv_bfloat16 g_qh[(size_t)2 * 8388608];
__device__ __nv_bfloat16 g_ql[(size_t)2 * 8388608];
__device__ __nv_bfloat16 g_kh[(size_t)2 * 8388608];
__device__ __nv_bfloat16 g_kl[(size_t)2 * 8388608];
__device__ __nv_bfloat16 g_vh[(size_t)2 * 8388608];
__device__ __nv_bfloat16 g_vl[(size_t)2 * 8388608];
__device__ __nv_bfloat16 g_xh[(size_t)33554432];
__device__ __nv_bfloat16 g_xl[(size_t)33554432];
__device__ __nv_bfloat16 g_ah[(size_t)33554432];
__device__ __nv_bfloat16 g_al[(size_t)33554432];
__device__ __nv_bfloat16 g_w3h[9 * 128 * 128];
__device__ __nv_bfloat16 g_w3l[9 * 128 * 128];
__device__ __nv_bfloat16 g_w1h[3 * 128 * 128];
__device__ __nv_bfloat16 g_w1l[3 * 128 * 128];

// ---------------- helpers ----------------
__device__ __forceinline__ void ffma2(ull& d, ull a, ull b) {
    asm("fma.rn.f32x2 %0, %1, %2, %0;" : "+l"(d) : "l"(a), "l"(b));
}
__device__ __forceinline__ float hsum2(ull v) {
    float2 f = *reinterpret_cast<float2*>(&v);
    return f.x + f.y;
}
__device__ __forceinline__ ull pack2(float a) {
    ull r; asm("mov.b64 %0,{%1,%1};" : "=l"(r) : "f"(a)); return r;
}
__device__ __forceinline__ void bsplit(float v, __nv_bfloat16& h, __nv_bfloat16& l) {
    h = __float2bfloat16(v);
    l = __float2bfloat16(v - __bfloat162float(h));
}
__device__ __forceinline__ u32 smem_u32(const void* p) {
    u32 a; asm("{ .reg .u64 t; cvta.to.shared.u64 t, %1; cvt.u32.u64 %0, t; }"
               : "=r"(a) : "l"(p));
    return a;
}
__device__ __forceinline__ void cpa16(u32 dst, const void* src) {
    asm volatile("cp.async.cg.shared.global [%0], [%1], 16;"
                 :: "r"(dst), "l"(src) : "memory");
}
#define CP_COMMIT() asm volatile("cp.async.commit_group;" ::: "memory")
#define CP_WAIT(n)  asm volatile("cp.async.wait_group %0;" :: "n"(n) : "memory")

typedef wmma::fragment<wmma::matrix_a, 16, 16, 16, __nv_bfloat16, wmma::row_major> FragA;
typedef wmma::fragment<wmma::matrix_b, 16, 16, 16, __nv_bfloat16, wmma::col_major> FragB;
typedef wmma::fragment<wmma::matrix_b, 16, 16, 16, __nv_bfloat16, wmma::row_major> FragBr;
typedef wmma::fragment<wmma::accumulator, 16, 16, 16, float> FragC;

// 3-product hi/lo microkernel: warp tile 32x64, K=128, ldm 136.
template<bool BROW, class FB>
__device__ __forceinline__ void mma3(const __nv_bfloat16* pAh, const __nv_bfloat16* pAl,
                                     const __nv_bfloat16* pBh, const __nv_bfloat16* pBl,
                                     FragC (&acc)[2][4])
{
#pragma unroll
    for (int kt = 0; kt < 8; kt++) {
        int k0 = kt * 16;
        FragA ah[2], al[2];
        FB bh[4], bl[4];
#pragma unroll
        for (int i = 0; i < 2; i++) {
            wmma::load_matrix_sync(ah[i], pAh + (16 * i) * 136 + k0, 136);
            wmma::load_matrix_sync(al[i], pAl + (16 * i) * 136 + k0, 136);
        }
#pragma unroll
        for (int j = 0; j < 4; j++) {
            int o = BROW ? (k0 * 136 + 16 * j) : ((16 * j) * 136 + k0);
            wmma::load_matrix_sync(bh[j], pBh + o, 136);
            wmma::load_matrix_sync(bl[j], pBl + o, 136);
        }
#pragma unroll
        for (int i = 0; i < 2; i++)
#pragma unroll
            for (int j = 0; j < 4; j++) {
                wmma::mma_sync(acc[i][j], ah[i], bh[j], acc[i][j]);
                wmma::mma_sync(acc[i][j], ah[i], bl[j], acc[i][j]);
                wmma::mma_sync(acc[i][j], al[i], bh[j], acc[i][j]);
            }
    }
}

// ============ prep: x -> channel-last bf16 hi/lo ============
__global__ __launch_bounds__(256)
void prep_x_kernel(const float* __restrict__ x)
{
    __shared__ float sb[64][130];
    int y = blockIdx.x, img = blockIdx.y, tid = threadIdx.x;
    for (int ch = 0; ch < 2; ch++) {
        for (int idx = tid; idx < 64 * 128; idx += 256) {
            int cl = idx >> 7, xp = idx & 127;
            sb[cl][xp] = x[((size_t)img * 128 + ch * 64 + cl) * HWs + y * 128 + xp];
        }
        __syncthreads();
        for (int idx = tid; idx < 64 * 128; idx += 256) {
            int px = idx >> 6, cl = idx & 63;
            __nv_bfloat16 h, l;
            bsplit(sb[cl][px], h, l);
            size_t o = (((size_t)img * 128 + y) * 128 + px) * 128 + ch * 64 + cl;
            g_xh[o] = h; g_xl[o] = l;
        }
        __syncthreads();
    }
}

// ============ prep: weights ============
__global__ void prep_w3_kernel(const float* __restrict__ wo)
{
    int i = blockIdx.x * 256 + threadIdx.x;
    if (i >= 9 * 128 * 128) return;
    int tap = i / 16384, r = i % 16384, oc = r >> 7, ic = r & 127;
    __nv_bfloat16 h, l;
    bsplit(wo[((size_t)oc * 128 + ic) * 9 + tap], h, l);
    size_t o = ((size_t)tap * 128 + oc) * 128 + ic;
    g_w3h[o] = h; g_w3l[o] = l;
}
__global__ void prep_w1_kernel(const float* __restrict__ wq,
                               const float* __restrict__ wk,
                               const float* __restrict__ wv)
{
    int i = blockIdx.x * 256 + threadIdx.x;
    if (i >= 3 * 16384) return;
    int o = i / 16384, r = i % 16384;
    const float* w = (o == 0) ? wq : (o == 1) ? wk : wv;
    __nv_bfloat16 h, l;
    bsplit(w[r], h, l);
    g_w1h[i] = h; g_w1l[i] = l;
}

// ============ conv1x1 v7: GEMM + conflict-free transpose + vector scatter ====
__global__ __launch_bounds__(128, 2)
void conv1_v7_kernel(const float* __restrict__ bq, const float* __restrict__ bk,
                     const float* __restrict__ bv)
{
    extern __shared__ __align__(16) char smem[];
    u32 sb = smem_u32(smem);
    const u32 AH = 0, AL = 34816, BH = 69632, BL = 87040;

    int bx = blockIdx.x, img = blockIdx.y;
    int y = bx / 6, z = bx - 6 * y;
    int o = z >> 1, oh = z & 1;
    int tid = threadIdx.x, wid = tid >> 5;
    int px0 = wid * 32;

    size_t abase = (((size_t)img * 128 + y) * 128) * 128;
    for (int idx = tid; idx < 2048; idx += 128) {
        int row = idx >> 4, k8 = (idx & 15) << 3;
        u32 d = (u32)(row * 136 + k8) * 2;
        cpa16(sb + AH + d, g_xh + abase + row * 128 + k8);
        cpa16(sb + AL + d, g_xl + abase + row * 128 + k8);
    }
    const __nv_bfloat16* wh = g_w1h + (size_t)o * 16384 + oh * 8192;
    const __nv_bfloat16* wl = g_w1l + (size_t)o * 16384 + oh * 8192;
    for (int idx = tid; idx < 1024; idx += 128) {
        int row = idx >> 4, k8 = (idx & 15) << 3;
        u32 d = (u32)(row * 136 + k8) * 2;
        cpa16(sb + BH + d, wh + row * 128 + k8);
        cpa16(sb + BL + d, wl + row * 128 + k8);
    }
    CP_COMMIT(); CP_WAIT(0);
    __syncthreads();

    FragC acc[2][4];
#pragma unroll
    for (int i = 0; i < 2; i++)
#pragma unroll
        for (int j = 0; j < 4; j++) wmma::fill_fragment(acc[i][j], 0.f);

    mma3<false, FragB>((const __nv_bfloat16*)(smem + AH) + px0 * 136,
                       (const __nv_bfloat16*)(smem + AL) + px0 * 136,
                       (const __nv_bfloat16*)(smem + BH),
                       (const __nv_bfloat16*)(smem + BL), acc);
    __syncthreads();

    float* Cs = (float*)(smem + BH);   // [128][68]
#pragma unroll
    for (int i = 0; i < 2; i++)
#pragma unroll
        for (int j = 0; j < 4; j++)
            wmma::store_matrix_sync(&Cs[(px0 + 16 * i) * 68 + 16 * j],
                                    acc[i][j], 68, wmma::mem_row_major);
    __syncthreads();

    // stage 1: transpose C -> T[oc][px] (conflict-free both sides)
    float* T = (float*)(smem + AH);    // [64][132]
#pragma unroll
    for (int j4 = 0; j4 < 64; j4 += 4) {
        float4 v = *(float4*)&Cs[tid * 68 + j4];
        T[(j4 + 0) * 132 + tid] = v.x;
        T[(j4 + 1) * 132 + tid] = v.y;
        T[(j4 + 2) * 132 + tid] = v.z;
        T[(j4 + 3) * 132 + tid] = v.w;
    }
    __syncthreads();

    // stage 2: vector scatter (+bias; bf16 hi/lo for scales 2,3)
    int b = img >> 3, t = img & 7;
    const float* bias = (o == 0) ? bq : (o == 1) ? bk : bv;
    float* dstf = (o == 0) ? g_qw : (o == 1) ? g_kw : g_vw;
    __nv_bfloat16* dsth = (o == 0) ? g_qh : (o == 1) ? g_kh : g_vh;
    __nv_bfloat16* dstl = (o == 0) ? g_ql : (o == 1) ? g_kl : g_vl;

    int px4 = (tid & 31) * 4;
#pragma unroll
    for (int k = 0; k < 16; k++) {
        int ocl = 4 * k + (tid >> 5);
        int oc = oh * 64 + ocl;
        int s = oc >> 5, lph = 7 - s;
        int phm = (1 << lph) - 1;
        int n_s = 8 << (2 * s), d_s = 524288 >> (2 * s);
        int oy = y >> lph, py = y & phm;
        int tokb = ((t << s) + oy) << s;
        int eb = (((oc & 31) << lph) + py) << lph;
        float bv2 = bias[oc];
        int ox = px4 >> lph, pxm = px4 & phm;
        size_t a = ((size_t)(b * n_s + tokb + ox)) * d_s + eb + pxm;
        float4 v = *(float4*)&T[ocl * 132 + px4];
        v.x += bv2; v.y += bv2; v.z += bv2; v.w += bv2;
        if (s < 2) {
            *(float4*)(dstf + (size_t)s * 8388608 + a) = v;
        } else {
            __nv_bfloat16 h0, l0, h1, l1, h2, l2, h3, l3;
            bsplit(v.x, h0, l0); bsplit(v.y, h1, l1);
            bsplit(v.z, h2, l2); bsplit(v.w, h3, l3);
            __nv_bfloat162 hp0 = __halves2bfloat162(h0, h1);
            __nv_bfloat162 hp1 = __halves2bfloat162(h2, h3);
            __nv_bfloat162 lp0 = __halves2bfloat162(l0, l1);
            __nv_bfloat162 lp1 = __halves2bfloat162(l2, l3);
            uint2 hv, lv;
            hv.x = *(u32*)&hp0; hv.y = *(u32*)&hp1;
            lv.x = *(u32*)&lp0; lv.y = *(u32*)&lp1;
            *(uint2*)(dsth + (size_t)(s - 2) * 8388608 + a) = hv;
            *(uint2*)(dstl + (size_t)(s - 2) * 8388608 + a) = lv;
        }
    }
}

// ============ scale-0 scores (n=8, d=524288, fp32) ============
__global__ __launch_bounds__(256)
void scores0_kernel()
{
    __shared__ float Qs[8][516];
    __shared__ float Ks[8][516];
    __shared__ float sred[256];
    int z = blockIdx.x, b = blockIdx.y, tid = threadIdx.x;
    const int d = 524288;

    const float* qb = g_qw + ((size_t)(b * 8)) * d + z * 512;
    const float* kb = g_kw + ((size_t)(b * 8)) * d + z * 512;
    for (int idx = tid; idx < 1024; idx += 256) {
        int r = idx >> 7, c4 = (idx & 127) * 4;
        *(float4*)&Qs[r][c4] = *(const float4*)(qb + (size_t)r * d + c4);
        *(float4*)&Ks[r][c4] = *(const float4*)(kb + (size_t)r * d + c4);
    }
    __syncthreads();

    int rm = tid & 63, r = rm >> 3, m = rm & 7, kg = tid >> 6;
    ull acc = 0ull;
    int kb0 = kg * 128;
#pragma unroll
    for (int kk2 = 0; kk2 < 64; kk2++)
        ffma2(acc, *(const ull*)&Qs[r][kb0 + 2 * kk2], *(const ull*)&Ks[m][kb0 + 2 * kk2]);
    sred[tid] = hsum2(acc);
    __syncthreads();
    if (tid < 64)
        g_part[(size_t)(z * NBm + b) * 64 + tid] =
            sred[tid] + sred[tid + 64] + sred[tid + 128] + sred[tid + 192];
}

// ============ scale-1 scores (scalar, split-k) ============
template<int BN, int TN>
__global__ __launch_bounds__(256)
void scores2_kernel(int n, int d, long long off_ll, int tilesM, int dchunk)
{
    __shared__ float Qs[BN][68];
    __shared__ float Ks[BN][68];
    size_t off = (size_t)off_ll;
    int b = blockIdx.y, z = blockIdx.z;
    int tn = blockIdx.x / tilesM, tm = blockIdx.x - tn * tilesM;
    int n0 = tn * BN, m0 = tm * BN;
    int tx = threadIdx.x, ty = threadIdx.y, tid = ty * 16 + tx;

    ull acc[TN][TN];
#pragma unroll
    for (int i = 0; i < TN; i++)
#pragma unroll
        for (int j = 0; j < TN; j++) acc[i][j] = 0ull;

    const float* qb = g_qw + off + ((size_t)(b * n + n0)) * d;
    const float* kb = g_kw + off + ((size_t)(b * n + m0)) * d;
    int r0 = ty * TN;
    int k0s = z * dchunk;

    for (int k0 = k0s; k0 < k0s + dchunk; k0 += 64) {
        for (int idx = tid; idx < BN * 16; idx += 256) {
            int r = idx >> 4, c4 = (idx & 15) * 4;
            *(float4*)&Qs[r][c4] = *(const float4*)(qb + (size_t)r * d + k0 + c4);
            *(float4*)&Ks[r][c4] = *(const float4*)(kb + (size_t)r * d + k0 + c4);
        }
        __syncthreads();
#pragma unroll
        for (int kk2 = 0; kk2 < 32; kk2++) {
            ull q2[TN], k2[TN];
#pragma unroll
            for (int i = 0; i < TN; i++) q2[i] = *(const ull*)&Qs[r0 + i][2 * kk2];
#pragma unroll
            for (int j = 0; j < TN; j++) k2[j] = *(const ull*)&Ks[tx + 16 * j][2 * kk2];
#pragma unroll
            for (int i = 0; i < TN; i++)
#pragma unroll
                for (int j = 0; j < TN; j++) ffma2(acc[i][j], q2[i], k2[j]);
        }
        __syncthreads();
    }

    size_t base = ((size_t)(z * NBm + b)) * n * n;
#pragma unroll
    for (int i = 0; i < TN; i++)
#pragma unroll
        for (int j = 0; j < TN; j++)
            g_part[base + (size_t)(n0 + r0 + i) * n + (m0 + tx + 16 * j)] =
                hsum2(acc[i][j]);
}

// ============ WMMA scores (scales 2,3): M=64 tile, 2 CTAs/SM ============
__global__ __launch_bounds__(128, 2)
void scores_wmma_kernel(int n, int d, long long offb_ll, int tilesM, int dchunk)
{
    extern __shared__ __align__(16) char smem[];
    u32 sb = smem_u32(smem);
    const u32 QH = 0, QL = 17408, KH = 34816, KL = 69632;
    size_t offb = (size_t)offb_ll;
    int b = blockIdx.y, z = blockIdx.z;
    int tn = blockIdx.x / tilesM, tm = blockIdx.x - tn * tilesM;
    int n0 = tn * 64, m0 = tm * 128;
    int tid = threadIdx.x, wid = tid >> 5;
    int px0 = (wid & 1) * 32, oc0 = (wid >> 1) * 64;

    const __nv_bfloat16* qh = g_qh + offb + ((size_t)(b * n + n0)) * d;
    const __nv_bfloat16* ql = g_ql + offb + ((size_t)(b * n + n0)) * d;
    const __nv_bfloat16* kh = g_kh + offb + ((size_t)(b * n + m0)) * d;
    const __nv_bfloat16* kl = g_kl + offb + ((size_t)(b * n + m0)) * d;

    FragC acc[2][4];
#pragma unroll
    for (int i = 0; i < 2; i++)
#pragma unroll
        for (int j = 0; j < 4; j++) wmma::fill_fragment(acc[i][j], 0.f);

    int k0s = z * dchunk;
    for (int k0 = k0s; k0 < k0s + dchunk; k0 += 128) {
        for (int idx = tid; idx < 1024; idx += 128) {
            int r = idx >> 4, k8 = (idx & 15) << 3;
            u32 dd = (u32)(r * 136 + k8) * 2;
            size_t go = (size_t)r * d + k0 + k8;
            cpa16(sb + QH + dd, qh + go);
            cpa16(sb + QL + dd, ql + go);
        }
        for (int idx = tid; idx < 2048; idx += 128) {
            int r = idx >> 4, k8 = (idx & 15) << 3;
            u32 dd = (u32)(r * 136 + k8) * 2;
            size_t go = (size_t)r * d + k0 + k8;
            cpa16(sb + KH + dd, kh + go);
            cpa16(sb + KL + dd, kl + go);
        }
        CP_COMMIT(); CP_WAIT(0);
        __syncthreads();
        mma3<false, FragB>((const __nv_bfloat16*)(smem + QH) + px0 * 136,
                           (const __nv_bfloat16*)(smem + QL) + px0 * 136,
                           (const __nv_bfloat16*)(smem + KH) + oc0 * 136,
                           (const __nv_bfloat16*)(smem + KL) + oc0 * 136, acc);
        __syncthreads();
    }

    size_t base = ((size_t)(z * NBm + b)) * n * n;
#pragma unroll
    for (int i = 0; i < 2; i++)
#pragma unroll
        for (int j = 0; j < 4; j++)
            wmma::store_matrix_sync(
                g_part + base + (size_t)(n0 + px0 + 16 * i) * n + m0 + oc0 + 16 * j,
                acc[i][j], n, wmma::mem_row_major);
}

// ============ reduce + softmax (+ optional bf16 attn output) ============
__global__ __launch_bounds__(256)
void softmax_kernel(int n, int nsplit, float isd, int wbf)
{
    __shared__ float sbuf[512];
    __shared__ float red[256];
    int row = blockIdx.x, b = blockIdx.y, tid = threadIdx.x;

    if (n <= 32) {
        int m = tid % n, zi = tid / n, tpm = 256 / n;
        float s = 0.f;
        for (int z = zi; z < nsplit; z += tpm)
            s += g_part[((size_t)(z * NBm + b) * n + row) * n + m];
        red[tid] = s;
        __syncthreads();
        if (tid < n) {
            float t = 0.f;
            for (int j = 0; j < tpm; j++) t += red[tid + j * n];
            sbuf[tid] = t * isd;
        }
    } else {
        for (int m = tid; m < n; m += 256) {
            float s = 0.f;
            for (int z = 0; z < nsplit; z++)
                s += g_part[((size_t)(z * NBm + b) * n + row) * n + m];
            sbuf[m] = s * isd;
        }
    }
    __syncthreads();

    float lm = -1e30f;
    for (int m = tid; m < n; m += 256) lm = fmaxf(lm, sbuf[m]);
    red[tid] = lm;
    __syncthreads();
    for (int s = 128; s > 0; s >>= 1) {
        if (tid < s) red[tid] = fmaxf(red[tid], red[tid + s]);
        __syncthreads();
    }
    float mx = red[0];
    __syncthreads();
    float ls = 0.f;
    for (int m = tid; m < n; m += 256) {
        float e = __expf(sbuf[m] - mx);
        sbuf[m] = e; ls += e;
    }
    red[tid] = ls;
    __syncthreads();
    for (int s = 128; s > 0; s >>= 1) {
        if (tid < s) red[tid] += red[tid + s];
        __syncthreads();
    }
    float inv = 1.0f / red[0];
    for (int m = tid; m < n; m += 256) {
        float p = sbuf[m] * inv;
        size_t o = ((size_t)b * n + row) * n + m;
        if (wbf) {
            __nv_bfloat16 h, l;
            bsplit(p, h, l);
            g_ath[o] = h; g_atl[o] = l;
        } else {
            g_attn[o] = p;
        }
    }
}

// ============ scalar AV (scales 0,1) ============
template<int BN, int TN>
__global__ __launch_bounds__(256)
void av2_kernel(int n, int d, long long off_ll)
{
    __shared__ float As[BN][34];
    __shared__ float Vs[32][66];
    size_t off = (size_t)off_ll;
    int b = blockIdx.z, n0 = blockIdx.y * BN, e0 = blockIdx.x * 64;
    int tx = threadIdx.x, ty = threadIdx.y, tid = ty * 16 + tx;

    ull acc[TN][2];
#pragma unroll
    for (int i = 0; i < TN; i++) { acc[i][0] = 0ull; acc[i][1] = 0ull; }
    int r0 = ty * TN;

    const float* vb = g_vw + off + e0;

    for (int m0 = 0; m0 < n; m0 += 32) {
        for (int idx = tid; idx < BN * 8; idx += 256) {
            int r = idx >> 3, c4 = (idx & 7) * 4;
            float4 v = (m0 + c4 < n)
                ? *(const float4*)(g_attn + ((size_t)(b * n + n0 + r)) * n + m0 + c4)
                : make_float4(0.f, 0.f, 0.f, 0.f);
            As[r][c4] = v.x; As[r][c4 + 1] = v.y; As[r][c4 + 2] = v.z; As[r][c4 + 3] = v.w;
        }
        for (int idx = tid; idx < 512; idx += 256) {
            int mm = idx >> 4, e4 = (idx & 15) * 4;
            float4 v = (m0 + mm < n)
                ? *(const float4*)(vb + ((size_t)(b * n + m0 + mm)) * d + e4)
                : make_float4(0.f, 0.f, 0.f, 0.f);
            Vs[mm][e4] = v.x; Vs[mm][e4 + 1] = v.y; Vs[mm][e4 + 2] = v.z; Vs[mm][e4 + 3] = v.w;
        }
        __syncthreads();
#pragma unroll
        for (int kk = 0; kk < 32; kk++) {
            ull v2a = *(const ull*)&Vs[kk][2 * tx];
            ull v2b = *(const ull*)&Vs[kk][2 * tx + 32];
#pragma unroll
            for (int i = 0; i < TN; i++) {
                ull a2 = pack2(As[r0 + i][kk]);
                ffma2(acc[i][0], a2, v2a);
                ffma2(acc[i][1], a2, v2b);
            }
        }
        __syncthreads();
    }

    float* ob = g_ow + off;
#pragma unroll
    for (int i = 0; i < TN; i++) {
        size_t rb = ((size_t)(b * n + n0 + r0 + i)) * d + e0;
        *(float2*)(ob + rb + 2 * tx)      = *reinterpret_cast<float2*>(&acc[i][0]);
        *(float2*)(ob + rb + 2 * tx + 32) = *reinterpret_cast<float2*>(&acc[i][1]);
    }
}

// ============ WMMA AV (scales 2,3): M=64 tile, 2 CTAs/SM ============
__global__ __launch_bounds__(128, 2)
void av_wmma_kernel(int n, int d, long long offb_ll, long long off32_ll)
{
    extern __shared__ __align__(16) char smem[];
    u32 sb = smem_u32(smem);
    const u32 AH = 0, AL = 17408, VH = 34816, VL = 69632;
    size_t offb = (size_t)offb_ll, off32 = (size_t)off32_ll;
    int b = blockIdx.z, n0 = blockIdx.y * 64, e0 = blockIdx.x * 128;
    int tid = threadIdx.x, wid = tid >> 5;
    int px0 = (wid & 1) * 32, oc0 = (wid >> 1) * 64;

    FragC acc[2][4];
#pragma unroll
    for (int i = 0; i < 2; i++)
#pragma unroll
        for (int j = 0; j < 4; j++) wmma::fill_fragment(acc[i][j], 0.f);

    for (int m0 = 0; m0 < n; m0 += 128) {
        for (int idx = tid; idx < 1024; idx += 128) {
            int r = idx >> 4, k8 = (idx & 15) << 3;
            u32 dd = (u32)(r * 136 + k8) * 2;
            size_t ao = ((size_t)(b * n + n0 + r)) * n + m0 + k8;
            cpa16(sb + AH + dd, g_ath + ao);
            cpa16(sb + AL + dd, g_atl + ao);
        }
        for (int idx = tid; idx < 2048; idx += 128) {
            int r = idx >> 4, k8 = (idx & 15) << 3;
            u32 dd = (u32)(r * 136 + k8) * 2;
            size_t vo = offb + ((size_t)(b * n + m0 + r)) * d + e0 + k8;
            cpa16(sb + VH + dd, g_vh + vo);
            cpa16(sb + VL + dd, g_vl + vo);
        }
        CP_COMMIT(); CP_WAIT(0);
        __syncthreads();
        mma3<true, FragBr>((const __nv_bfloat16*)(smem + AH) + px0 * 136,
                           (const __nv_bfloat16*)(smem + AL) + px0 * 136,
                           (const __nv_bfloat16*)(smem + VH) + oc0,
                           (const __nv_bfloat16*)(smem + VL) + oc0, acc);
        __syncthreads();
    }

#pragma unroll
    for (int i = 0; i < 2; i++)
#pragma unroll
        for (int j = 0; j < 4; j++)
            wmma::store_matrix_sync(
                g_ow + off32 + ((size_t)(b * n + n0 + px0 + 16 * i)) * d + e0 + oc0 + 16 * j,
                acc[i][j], d, wmma::mem_row_major);
}

// ============ unpack windowed -> channel-last bf16 hi/lo ============
__global__ __launch_bounds__(256)
void unpack2_kernel()
{
    __shared__ float sbm[64][130];
    int y = blockIdx.x, img = blockIdx.y, tid = threadIdx.x;
    int b = img >> 3, t = img & 7;
    for (int ch = 0; ch < 2; ch++) {
        for (int idx = tid; idx < 64 * 128; idx += 256) {
            int cl = idx >> 7, xp = idx & 127;
            int c = ch * 64 + cl;
            int s = c >> 5, lph = 7 - s;
            int phm = (1 << lph) - 1;
            int n_s = 8 << (2 * s), d_s = 524288 >> (2 * s);
            int oy = y >> lph, py = y & phm;
            int ox = xp >> lph, pxm = xp & phm;
            int tok = ((((t << s) + oy) << s) + ox);
            int e = ((((c & 31) << lph) + py) << lph) + pxm;
            sbm[cl][xp] = g_ow[(size_t)s * 8388608 + ((size_t)(b * n_s + tok)) * d_s + e];
        }
        __syncthreads();
        for (int idx = tid; idx < 64 * 128; idx += 256) {
            int px = idx >> 6, cl = idx & 63;
            __nv_bfloat16 h, l;
            bsplit(sbm[cl][px], h, l);
            size_t o = (((size_t)img * 128 + y) * 128 + px) * 128 + ch * 64 + cl;
            g_ah[o] = h; g_al[o] = l;
        }
        __syncthreads();
    }
}

// ============ conv3x3 v5: conflict-free epilogue, 2 CTAs/SM ============
// smem: AH 0, AL 35360, BH 70720, BL 88128; Cs [128][76] at BH (38912 B).
__global__ __launch_bounds__(128, 2)
void conv3_v5_kernel(const float* __restrict__ bias, float* __restrict__ out)
{
    extern __shared__ __align__(16) char smem[];
    u32 sb = smem_u32(smem);
    const u32 AH = 0, AL = 35360, BH = 70720, BL = 88128;

    int bx = blockIdx.x, img = blockIdx.y;
    int y = bx >> 1, oh = bx & 1;
    int tid = threadIdx.x, wid = tid >> 5;
    int px0 = wid * 32;

    FragC acc[2][4];
#pragma unroll
    for (int i = 0; i < 2; i++)
#pragma unroll
        for (int j = 0; j < 4; j++) wmma::fill_fragment(acc[i][j], 0.f);

    for (int tp = 0; tp < 9; tp++) {
        int ky = tp / 3, kx = tp - ky * 3;
        __syncthreads();
        if (kx == 0) {
            int yy = y + ky - 1;
            bool yok = (yy >= 0 && yy < 128);
            size_t abase = (((size_t)img * 128 + (yok ? yy : 0)) * 128) * 128;
            for (int idx = tid; idx < 2080; idx += 128) {
                int i = idx >> 4, k8 = (idx & 15) << 3;
                int px = i - 1;
                u32 d = (u32)(i * 136 + k8) * 2;
                if (yok && px >= 0 && px < 128) {
                    size_t o = abase + (size_t)px * 128 + k8;
                    cpa16(sb + AH + d, g_ah + o);
                    cpa16(sb + AL + d, g_al + o);
                } else {
                    uint4 zz = make_uint4(0, 0, 0, 0);
                    *(uint4*)(smem + AH + d) = zz;
                    *(uint4*)(smem + AL + d) = zz;
                }
            }
        }
        const __nv_bfloat16* wh = g_w3h + (size_t)tp * 16384 + oh * 8192;
        const __nv_bfloat16* wl = g_w3l + (size_t)tp * 16384 + oh * 8192;
        for (int idx = tid; idx < 1024; idx += 128) {
            int row = idx >> 4, k8 = (idx & 15) << 3;
            u32 d = (u32)(row * 136 + k8) * 2;
            cpa16(sb + BH + d, wh + row * 128 + k8);
            cpa16(sb + BL + d, wl + row * 128 + k8);
        }
        CP_COMMIT(); CP_WAIT(0);
        __syncthreads();

        mma3<false, FragB>((const __nv_bfloat16*)(smem + AH) + (px0 + kx) * 136,
                           (const __nv_bfloat16*)(smem + AL) + (px0 + kx) * 136,
                           (const __nv_bfloat16*)(smem + BH),
                           (const __nv_bfloat16*)(smem + BL), acc);
    }
    __syncthreads();

    float* Cs = (float*)(smem + BH);    // [128][76]
#pragma unroll
    for (int i = 0; i < 2; i++)
#pragma unroll
        for (int j = 0; j < 4; j++)
            wmma::store_matrix_sync(&Cs[(px0 + 16 * i) * 76 + 16 * j],
                                    acc[i][j], 76, wmma::mem_row_major);
    __syncthreads();

    // stage 1: transpose (conflict-free: 76 -> 12t mod 32 all-distinct phases)
    float* T = (float*)(smem + AH);     // [64][132]
#pragma unroll
    for (int j4 = 0; j4 < 64; j4 += 4) {
        float4 v = *(float4*)&Cs[tid * 76 + j4];
        T[(j4 + 0) * 132 + tid] = v.x;
        T[(j4 + 1) * 132 + tid] = v.y;
        T[(j4 + 2) * 132 + tid] = v.z;
        T[(j4 + 3) * 132 + tid] = v.w;
    }
    __syncthreads();

    // stage 2: bias+relu, vector store
    int px4 = (tid & 31) * 4;
#pragma unroll
    for (int k = 0; k < 16; k++) {
        int ocl = 4 * k + (tid >> 5);
        float bv2 = bias[oh * 64 + ocl];
        float4 v = *(float4*)&T[ocl * 132 + px4];
        v.x = fmaxf(v.x + bv2, 0.f); v.y = fmaxf(v.y + bv2, 0.f);
        v.z = fmaxf(v.z + bv2, 0.f); v.w = fmaxf(v.w + bv2, 0.f);
        *(float4*)(out + ((size_t)img * 128 + oh * 64 + ocl) * HWs
                   + (size_t)y * 128 + px4) = v;
    }
}

// ============ launch ============
extern "C" void kernel_launch(void* const* d_in, const int* in_sizes, int n_in,
                              void* d_out, int out_size)
{
    const float* x  = (const float*)d_in[0];
    const float* wq = (const float*)d_in[1];
    const float* bq = (const float*)d_in[2];
    const float* wk = (const float*)d_in[3];
    const float* bk = (const float*)d_in[4];
    const float* wv = (const float*)d_in[5];
    const float* bv = (const float*)d_in[6];
    const float* wo = (const float*)d_in[7];
    const float* bo = (const float*)d_in[8];
    float* out = (float*)d_out;

    const int smem1 = 104448, smem3 = 109632, smemW = 104448;
    cudaFuncSetAttribute(conv1_v7_kernel,
                         cudaFuncAttributeMaxDynamicSharedMemorySize, smem1);
    cudaFuncSetAttribute(conv3_v5_kernel,
                         cudaFuncAttributeMaxDynamicSharedMemorySize, smem3);
    cudaFuncSetAttribute(scores_wmma_kernel,
                         cudaFuncAttributeMaxDynamicSharedMemorySize, smemW);
    cudaFuncSetAttribute(av_wmma_kernel,
                         cudaFuncAttributeMaxDynamicSharedMemorySize, smemW);

    dim3 blk(16, 16);

    prep_w3_kernel<<<(9 * 128 * 128 + 255) / 256, 256>>>(wo);
    prep_w1_kernel<<<(3 * 16384 + 255) / 256, 256>>>(wq, wk, wv);
    prep_x_kernel<<<dim3(Hd, BT), 256>>>(x);
    conv1_v7_kernel<<<dim3(768, BT), 128, smem1>>>(bq, bk, bv);

    // scale 0: n=8, d=524288 (scalar fp32)
    {
        float isd = 1.0f / sqrtf(524288.f);
        scores0_kernel<<<dim3(1024, NBm), 256>>>();
        softmax_kernel<<<dim3(8, NBm), 256>>>(8, 1024, isd, 0);
        av2_kernel<8, 1><<<dim3(524288 / 64, 1, NBm), blk>>>(8, 524288, 0LL);
    }
    // scale 1: n=32, d=131072 (scalar fp32)
    {
        float isd = 1.0f / sqrtf(131072.f);
        scores2_kernel<32, 2><<<dim3(1, NBm, 256), blk>>>(32, 131072, 8388608LL, 1, 512);
        softmax_kernel<<<dim3(32, NBm), 256>>>(32, 256, isd, 0);
        av2_kernel<32, 2><<<dim3(131072 / 64, 1, NBm), blk>>>(32, 131072, 8388608LL);
    }
    // scale 2: n=128, d=32768 (WMMA, M=64 tiles)
    {
        float isd = 1.0f / sqrtf(32768.f);
        scores_wmma_kernel<<<dim3(2, NBm, 128), 128, smemW>>>(128, 32768, 0LL, 1, 256);
        softmax_kernel<<<dim3(128, NBm), 256>>>(128, 128, isd, 1);
        av_wmma_kernel<<<dim3(256, 2, NBm), 128, smemW>>>(128, 32768, 0LL, 2LL * 8388608);
    }
    // scale 3: n=512, d=8192 (WMMA, M=64 tiles)
    {
        float isd = 1.0f / sqrtf(8192.f);
        scores_wmma_kernel<<<dim3(32, NBm, 8), 128, smemW>>>(512, 8192, 8388608LL, 4, 1024);
        softmax_kernel<<<dim3(512, NBm), 256>>>(512, 8, isd, 1);
        av_wmma_kernel<<<dim3(64, 8, NBm), 128, smemW>>>(512, 8192, 8388608LL, 3LL * 8388608);
    }

    unpack2_kernel<<<dim3(Hd, BT), 256>>>();
    conv3_v5_kernel<<<dim3(256, BT), 128, smem3>>>(bo, out);

    (void)in_sizes; (void)n_in; (void)out_size;
}

// round 17
// speedup vs baseline: 1.3519x; 1.3519x over previous
#include <cuda_runtime.h>
#include <cuda_fp16.h>
#include <mma.h>
#include <math.h>

using namespace nvcuda;

typedef unsigned long long ull;
typedef unsigned int u32;

#define Cc 128
#define Hd 128
#define Wd 128
#define HWs 16384
#define BT 16
#define NBm 2

// ---------------- device scratch ----------------
__device__ float g_qw[(size_t)2 * 8388608];
__device__ float g_kw[(size_t)2 * 8388608];
__device__ float g_vw[(size_t)2 * 8388608];
__device__ float g_ow[(size_t)4 * 8388608];
__device__ float g_part[(size_t)1 << 24];
__device__ float g_attn[(size_t)NBm * 512 * 512];
__device__ __half g_ath[(size_t)NBm * 512 * 512];
__device__ __half g_atl[(size_t)NBm * 512 * 512];
__device__ __half g_qh[(size_t)2 * 8388608];
__device__ __half g_ql[(size_t)2 * 8388608];
__device__ __half g_kh[(size_t)2 * 8388608];
__device__ __half g_vh[(size_t)2 * 8388608];
__device__ __half g_xh[(size_t)33554432];
__device__ __half g_xl[(size_t)33554432];
__device__ __half g_ah[(size_t)33554432];
__device__ __half g_al[(size_t)33554432];
__device__ __half g_w3h[9 * 128 * 128];
__device__ __half g_w1h[3 * 128 * 128];

// ---------------- helpers ----------------
__device__ __forceinline__ void ffma2(ull& d, ull a, ull b) {
    asm("fma.rn.f32x2 %0, %1, %2, %0;" : "+l"(d) : "l"(a), "l"(b));
}
__device__ __forceinline__ float hsum2(ull v) {
    float2 f = *reinterpret_cast<float2*>(&v);
    return f.x + f.y;
}
__device__ __forceinline__ ull pack2(float a) {
    ull r; asm("mov.b64 %0,{%1,%1};" : "=l"(r) : "f"(a)); return r;
}
__device__ __forceinline__ void hsplit(float v, __half& h, __half& l) {
    h = __float2half(v);
    l = __float2half(v - __half2float(h));
}
__device__ __forceinline__ u32 smem_u32(const void* p) {
    u32 a; asm("{ .reg .u64 t; cvta.to.shared.u64 t, %1; cvt.u32.u64 %0, t; }"
               : "=r"(a) : "l"(p));
    return a;
}
__device__ __forceinline__ void cpa16(u32 dst, const void* src) {
    asm volatile("cp.async.cg.shared.global [%0], [%1], 16;"
                 :: "r"(dst), "l"(src) : "memory");
}
#define CP_COMMIT() asm volatile("cp.async.commit_group;" ::: "memory")
#define CP_WAIT(n)  asm volatile("cp.async.wait_group %0;" :: "n"(n) : "memory")

typedef wmma::fragment<wmma::matrix_a, 16, 16, 16, __half, wmma::row_major> HFragA;
typedef wmma::fragment<wmma::matrix_b, 16, 16, 16, __half, wmma::col_major> HFragB;
typedef wmma::fragment<wmma::matrix_b, 16, 16, 16, __half, wmma::row_major> HFragBr;
typedef wmma::fragment<wmma::accumulator, 16, 16, 16, float> FragC;

// 2-product microkernel: A split hi/lo (fp16), B single fp16.
// warp tile 32x64, K=128, ldm 136.
template<bool BROW, class FB>
__device__ __forceinline__ void mma2(const __half* pAh, const __half* pAl,
                                     const __half* pB, FragC (&acc)[2][4])
{
#pragma unroll
    for (int kt = 0; kt < 8; kt++) {
        int k0 = kt * 16;
        HFragA ah[2], al[2];
        FB b[4];
#pragma unroll
        for (int i = 0; i < 2; i++) {
            wmma::load_matrix_sync(ah[i], pAh + (16 * i) * 136 + k0, 136);
            wmma::load_matrix_sync(al[i], pAl + (16 * i) * 136 + k0, 136);
        }
#pragma unroll
        for (int j = 0; j < 4; j++) {
            int o = BROW ? (k0 * 136 + 16 * j) : ((16 * j) * 136 + k0);
            wmma::load_matrix_sync(b[j], pB + o, 136);
        }
#pragma unroll
        for (int i = 0; i < 2; i++)
#pragma unroll
            for (int j = 0; j < 4; j++) {
                wmma::mma_sync(acc[i][j], ah[i], b[j], acc[i][j]);
                wmma::mma_sync(acc[i][j], al[i], b[j], acc[i][j]);
            }
    }
}

// ============ prep: x -> channel-last fp16 hi/lo ============
__global__ __launch_bounds__(256)
void prep_x_kernel(const float* __restrict__ x)
{
    __shared__ float sb[64][130];
    int y = blockIdx.x, img = blockIdx.y, tid = threadIdx.x;
    for (int ch = 0; ch < 2; ch++) {
        for (int idx = tid; idx < 64 * 128; idx += 256) {
            int cl = idx >> 7, xp = idx & 127;
            sb[cl][xp] = x[((size_t)img * 128 + ch * 64 + cl) * HWs + y * 128 + xp];
        }
        __syncthreads();
        for (int idx = tid; idx < 64 * 128; idx += 256) {
            int px = idx >> 6, cl = idx & 63;
            __half h, l;
            hsplit(sb[cl][px], h, l);
            size_t o = (((size_t)img * 128 + y) * 128 + px) * 128 + ch * 64 + cl;
            g_xh[o] = h; g_xl[o] = l;
        }
        __syncthreads();
    }
}

// ============ prep: weights (single fp16) ============
__global__ void prep_w3_kernel(const float* __restrict__ wo)
{
    int i = blockIdx.x * 256 + threadIdx.x;
    if (i >= 9 * 128 * 128) return;
    int tap = i / 16384, r = i % 16384, oc = r >> 7, ic = r & 127;
    g_w3h[((size_t)tap * 128 + oc) * 128 + ic] =
        __float2half(wo[((size_t)oc * 128 + ic) * 9 + tap]);
}
__global__ void prep_w1_kernel(const float* __restrict__ wq,
                               const float* __restrict__ wk,
                               const float* __restrict__ wv)
{
    int i = blockIdx.x * 256 + threadIdx.x;
    if (i >= 3 * 16384) return;
    int o = i / 16384, r = i % 16384;
    const float* w = (o == 0) ? wq : (o == 1) ? wk : wv;
    g_w1h[i] = __float2half(w[r]);
}

// ============ conv1x1 v8: fp16 2-prod GEMM + fused vector scatter ============
// smem: AH 0 (34816), AL 34816 (34816), BH 69632 (17408). Cs overlays AH.
__global__ __launch_bounds__(128, 2)
void conv1_v8_kernel(const float* __restrict__ bq, const float* __restrict__ bk,
                     const float* __restrict__ bv)
{
    extern __shared__ __align__(16) char smem[];
    u32 sb = smem_u32(smem);
    const u32 AH = 0, AL = 34816, BH = 69632;

    int bx = blockIdx.x, img = blockIdx.y;
    int y = bx / 6, z = bx - 6 * y;
    int o = z >> 1, oh = z & 1;
    int tid = threadIdx.x, wid = tid >> 5;
    int px0 = wid * 32;

    size_t abase = (((size_t)img * 128 + y) * 128) * 128;
    for (int idx = tid; idx < 2048; idx += 128) {
        int row = idx >> 4, k8 = (idx & 15) << 3;
        u32 d = (u32)(row * 136 + k8) * 2;
        cpa16(sb + AH + d, g_xh + abase + row * 128 + k8);
        cpa16(sb + AL + d, g_xl + abase + row * 128 + k8);
    }
    const __half* wh = g_w1h + (size_t)o * 16384 + oh * 8192;
    for (int idx = tid; idx < 1024; idx += 128) {
        int row = idx >> 4, k8 = (idx & 15) << 3;
        cpa16(sb + BH + (u32)(row * 136 + k8) * 2, wh + row * 128 + k8);
    }
    CP_COMMIT(); CP_WAIT(0);
    __syncthreads();

    FragC acc[2][4];
#pragma unroll
    for (int i = 0; i < 2; i++)
#pragma unroll
        for (int j = 0; j < 4; j++) wmma::fill_fragment(acc[i][j], 0.f);

    mma2<false, HFragB>((const __half*)(smem + AH) + px0 * 136,
                        (const __half*)(smem + AL) + px0 * 136,
                        (const __half*)(smem + BH), acc);
    __syncthreads();   // A reads done; reuse AH region for C

    float* Cs = (float*)(smem + AH);   // [128][68] = 34816 B
#pragma unroll
    for (int i = 0; i < 2; i++)
#pragma unroll
        for (int j = 0; j < 4; j++)
            wmma::store_matrix_sync(&Cs[(px0 + 16 * i) * 68 + 16 * j],
                                    acc[i][j], 68, wmma::mem_row_major);
    __syncthreads();

    // vector scatter (+bias). q -> hi/lo fp16 (scores A); k,v -> single fp16.
    int b = img >> 3, t = img & 7;
    const float* bias = (o == 0) ? bq : (o == 1) ? bk : bv;
    float* dstf = (o == 0) ? g_qw : (o == 1) ? g_kw : g_vw;
    __half* dsth = (o == 0) ? g_qh : (o == 1) ? g_kh : g_vh;

    int px4 = (tid & 31) * 4, og = tid >> 5;
    for (int j = 0; j < 16; j++) {
        int ocl = og * 16 + j;
        int oc = oh * 64 + ocl;
        int s = oc >> 5, lph = 7 - s;
        int phm = (1 << lph) - 1;
        int n_s = 8 << (2 * s), d_s = 524288 >> (2 * s);
        int oy = y >> lph, py = y & phm;
        int tokb = ((t << s) + oy) << s;
        int eb = (((oc & 31) << lph) + py) << lph;
        float bv2 = bias[oc];
        int ox = px4 >> lph, pxm = px4 & phm;
        size_t a = ((size_t)(b * n_s + tokb + ox)) * d_s + eb + pxm;
        float v0 = Cs[(px4 + 0) * 68 + ocl] + bv2;
        float v1 = Cs[(px4 + 1) * 68 + ocl] + bv2;
        float v2 = Cs[(px4 + 2) * 68 + ocl] + bv2;
        float v3 = Cs[(px4 + 3) * 68 + ocl] + bv2;
        if (s < 2) {
            *(float4*)(dstf + (size_t)s * 8388608 + a) =
                make_float4(v0, v1, v2, v3);
        } else {
            size_t ao = (size_t)(s - 2) * 8388608 + a;
            if (o == 0) {
                __half h0, l0, h1, l1, h2, l2, h3, l3;
                hsplit(v0, h0, l0); hsplit(v1, h1, l1);
                hsplit(v2, h2, l2); hsplit(v3, h3, l3);
                __half2 hp0 = __halves2half2(h0, h1), hp1 = __halves2half2(h2, h3);
                __half2 lp0 = __halves2half2(l0, l1), lp1 = __halves2half2(l2, l3);
                uint2 hv, lv;
                hv.x = *(u32*)&hp0; hv.y = *(u32*)&hp1;
                lv.x = *(u32*)&lp0; lv.y = *(u32*)&lp1;
                *(uint2*)(g_qh + ao) = hv;
                *(uint2*)(g_ql + ao) = lv;
            } else {
                __half2 p0 = __halves2half2(__float2half(v0), __float2half(v1));
                __half2 p1 = __halves2half2(__float2half(v2), __float2half(v3));
                uint2 hv;
                hv.x = *(u32*)&p0; hv.y = *(u32*)&p1;
                *(uint2*)(dsth + ao) = hv;
            }
        }
    }
}

// ============ scale-0 scores (n=8, d=524288, fp32) ============
__global__ __launch_bounds__(256)
void scores0_kernel()
{
    __shared__ float Qs[8][516];
    __shared__ float Ks[8][516];
    __shared__ float sred[256];
    int z = blockIdx.x, b = blockIdx.y, tid = threadIdx.x;
    const int d = 524288;

    const float* qb = g_qw + ((size_t)(b * 8)) * d + z * 512;
    const float* kb = g_kw + ((size_t)(b * 8)) * d + z * 512;
    for (int idx = tid; idx < 1024; idx += 256) {
        int r = idx >> 7, c4 = (idx & 127) * 4;
        *(float4*)&Qs[r][c4] = *(const float4*)(qb + (size_t)r * d + c4);
        *(float4*)&Ks[r][c4] = *(const float4*)(kb + (size_t)r * d + c4);
    }
    __syncthreads();

    int rm = tid & 63, r = rm >> 3, m = rm & 7, kg = tid >> 6;
    ull acc = 0ull;
    int kb0 = kg * 128;
#pragma unroll
    for (int kk2 = 0; kk2 < 64; kk2++)
        ffma2(acc, *(const ull*)&Qs[r][kb0 + 2 * kk2], *(const ull*)&Ks[m][kb0 + 2 * kk2]);
    sred[tid] = hsum2(acc);
    __syncthreads();
    if (tid < 64)
        g_part[(size_t)(z * NBm + b) * 64 + tid] =
            sred[tid] + sred[tid + 64] + sred[tid + 128] + sred[tid + 192];
}

// ============ scale-1 scores (scalar, split-k) ============
template<int BN, int TN>
__global__ __launch_bounds__(256)
void scores2_kernel(int n, int d, long long off_ll, int tilesM, int dchunk)
{
    __shared__ float Qs[BN][68];
    __shared__ float Ks[BN][68];
    size_t off = (size_t)off_ll;
    int b = blockIdx.y, z = blockIdx.z;
    int tn = blockIdx.x / tilesM, tm = blockIdx.x - tn * tilesM;
    int n0 = tn * BN, m0 = tm * BN;
    int tx = threadIdx.x, ty = threadIdx.y, tid = ty * 16 + tx;

    ull acc[TN][TN];
#pragma unroll
    for (int i = 0; i < TN; i++)
#pragma unroll
        for (int j = 0; j < TN; j++) acc[i][j] = 0ull;

    const float* qb = g_qw + off + ((size_t)(b * n + n0)) * d;
    const float* kb = g_kw + off + ((size_t)(b * n + m0)) * d;
    int r0 = ty * TN;
    int k0s = z * dchunk;

    for (int k0 = k0s; k0 < k0s + dchunk; k0 += 64) {
        for (int idx = tid; idx < BN * 16; idx += 256) {
            int r = idx >> 4, c4 = (idx & 15) * 4;
            *(float4*)&Qs[r][c4] = *(const float4*)(qb + (size_t)r * d + k0 + c4);
            *(float4*)&Ks[r][c4] = *(const float4*)(kb + (size_t)r * d + k0 + c4);
        }
        __syncthreads();
#pragma unroll
        for (int kk2 = 0; kk2 < 32; kk2++) {
            ull q2[TN], k2[TN];
#pragma unroll
            for (int i = 0; i < TN; i++) q2[i] = *(const ull*)&Qs[r0 + i][2 * kk2];
#pragma unroll
            for (int j = 0; j < TN; j++) k2[j] = *(const ull*)&Ks[tx + 16 * j][2 * kk2];
#pragma unroll
            for (int i = 0; i < TN; i++)
#pragma unroll
                for (int j = 0; j < TN; j++) ffma2(acc[i][j], q2[i], k2[j]);
        }
        __syncthreads();
    }

    size_t base = ((size_t)(z * NBm + b)) * n * n;
#pragma unroll
    for (int i = 0; i < TN; i++)
#pragma unroll
        for (int j = 0; j < TN; j++)
            g_part[base + (size_t)(n0 + r0 + i) * n + (m0 + tx + 16 * j)] =
                hsum2(acc[i][j]);
}

// ============ WMMA scores (scales 2,3): fp16 2-prod, 3 CTAs/SM ============
// smem: QH 0 (17408), QL 17408 (17408), KH 34816 (34816). total 69632.
__global__ __launch_bounds__(128, 3)
void scores_h_kernel(int n, int d, long long offb_ll, int tilesM, int dchunk)
{
    extern __shared__ __align__(16) char smem[];
    u32 sb = smem_u32(smem);
    const u32 QH = 0, QL = 17408, KH = 34816;
    size_t offb = (size_t)offb_ll;
    int b = blockIdx.y, z = blockIdx.z;
    int tn = blockIdx.x / tilesM, tm = blockIdx.x - tn * tilesM;
    int n0 = tn * 64, m0 = tm * 128;
    int tid = threadIdx.x, wid = tid >> 5;
    int px0 = (wid & 1) * 32, oc0 = (wid >> 1) * 64;

    const __half* qh = g_qh + offb + ((size_t)(b * n + n0)) * d;
    const __half* ql = g_ql + offb + ((size_t)(b * n + n0)) * d;
    const __half* kh = g_kh + offb + ((size_t)(b * n + m0)) * d;

    FragC acc[2][4];
#pragma unroll
    for (int i = 0; i < 2; i++)
#pragma unroll
        for (int j = 0; j < 4; j++) wmma::fill_fragment(acc[i][j], 0.f);

    int k0s = z * dchunk;
    for (int k0 = k0s; k0 < k0s + dchunk; k0 += 128) {
        for (int idx = tid; idx < 1024; idx += 128) {
            int r = idx >> 4, k8 = (idx & 15) << 3;
            u32 dd = (u32)(r * 136 + k8) * 2;
            size_t go = (size_t)r * d + k0 + k8;
            cpa16(sb + QH + dd, qh + go);
            cpa16(sb + QL + dd, ql + go);
        }
        for (int idx = tid; idx < 2048; idx += 128) {
            int r = idx >> 4, k8 = (idx & 15) << 3;
            cpa16(sb + KH + (u32)(r * 136 + k8) * 2, kh + (size_t)r * d + k0 + k8);
        }
        CP_COMMIT(); CP_WAIT(0);
        __syncthreads();
        mma2<false, HFragB>((const __half*)(smem + QH) + px0 * 136,
                            (const __half*)(smem + QL) + px0 * 136,
                            (const __half*)(smem + KH) + oc0 * 136, acc);
        __syncthreads();
    }

    size_t base = ((size_t)(z * NBm + b)) * n * n;
#pragma unroll
    for (int i = 0; i < 2; i++)
#pragma unroll
        for (int j = 0; j < 4; j++)
            wmma::store_matrix_sync(
                g_part + base + (size_t)(n0 + px0 + 16 * i) * n + m0 + oc0 + 16 * j,
                acc[i][j], n, wmma::mem_row_major);
}

// ============ reduce + softmax (+ optional fp16 hi/lo attn output) ============
__global__ __launch_bounds__(256)
void softmax_kernel(int n, int nsplit, float isd, int wbf)
{
    __shared__ float sbuf[512];
    __shared__ float red[256];
    int row = blockIdx.x, b = blockIdx.y, tid = threadIdx.x;

    if (n <= 32) {
        int m = tid % n, zi = tid / n, tpm = 256 / n;
        float s = 0.f;
        for (int z = zi; z < nsplit; z += tpm)
            s += g_part[((size_t)(z * NBm + b) * n + row) * n + m];
        red[tid] = s;
        __syncthreads();
        if (tid < n) {
            float t = 0.f;
            for (int j = 0; j < tpm; j++) t += red[tid + j * n];
            sbuf[tid] = t * isd;
        }
    } else {
        for (int m = tid; m < n; m += 256) {
            float s = 0.f;
            for (int z = 0; z < nsplit; z++)
                s += g_part[((size_t)(z * NBm + b) * n + row) * n + m];
            sbuf[m] = s * isd;
        }
    }
    __syncthreads();

    float lm = -1e30f;
    for (int m = tid; m < n; m += 256) lm = fmaxf(lm, sbuf[m]);
    red[tid] = lm;
    __syncthreads();
    for (int s = 128; s > 0; s >>= 1) {
        if (tid < s) red[tid] = fmaxf(red[tid], red[tid + s]);
        __syncthreads();
    }
    float mx = red[0];
    __syncthreads();
    float ls = 0.f;
    for (int m = tid; m < n; m += 256) {
        float e = __expf(sbuf[m] - mx);
        sbuf[m] = e; ls += e;
    }
    red[tid] = ls;
    __syncthreads();
    for (int s = 128; s > 0; s >>= 1) {
        if (tid < s) red[tid] += red[tid + s];
        __syncthreads();
    }
    float inv = 1.0f / red[0];
    for (int m = tid; m < n; m += 256) {
        float p = sbuf[m] * inv;
        size_t o = ((size_t)b * n + row) * n + m;
        if (wbf) {
            __half h, l;
            hsplit(p, h, l);
            g_ath[o] = h; g_atl[o] = l;
        } else {
            g_attn[o] = p;
        }
    }
}

// ============ scalar AV (scales 0,1) ============
template<int BN, int TN>
__global__ __launch_bounds__(256)
void av2_kernel(int n, int d, long long off_ll)
{
    __shared__ float As[BN][34];
    __shared__ float Vs[32][66];
    size_t off = (size_t)off_ll;
    int b = blockIdx.z, n0 = blockIdx.y * BN, e0 = blockIdx.x * 64;
    int tx = threadIdx.x, ty = threadIdx.y, tid = ty * 16 + tx;

    ull acc[TN][2];
#pragma unroll
    for (int i = 0; i < TN; i++) { acc[i][0] = 0ull; acc[i][1] = 0ull; }
    int r0 = ty * TN;

    const float* vb = g_vw + off + e0;

    for (int m0 = 0; m0 < n; m0 += 32) {
        for (int idx = tid; idx < BN * 8; idx += 256) {
            int r = idx >> 3, c4 = (idx & 7) * 4;
            float4 v = (m0 + c4 < n)
                ? *(const float4*)(g_attn + ((size_t)(b * n + n0 + r)) * n + m0 + c4)
                : make_float4(0.f, 0.f, 0.f, 0.f);
            As[r][c4] = v.x; As[r][c4 + 1] = v.y; As[r][c4 + 2] = v.z; As[r][c4 + 3] = v.w;
        }
        for (int idx = tid; idx < 512; idx += 256) {
            int mm = idx >> 4, e4 = (idx & 15) * 4;
            float4 v = (m0 + mm < n)
                ? *(const float4*)(vb + ((size_t)(b * n + m0 + mm)) * d + e4)
                : make_float4(0.f, 0.f, 0.f, 0.f);
            Vs[mm][e4] = v.x; Vs[mm][e4 + 1] = v.y; Vs[mm][e4 + 2] = v.z; Vs[mm][e4 + 3] = v.w;
        }
        __syncthreads();
#pragma unroll
        for (int kk = 0; kk < 32; kk++) {
            ull v2a = *(const ull*)&Vs[kk][2 * tx];
            ull v2b = *(const ull*)&Vs[kk][2 * tx + 32];
#pragma unroll
            for (int i = 0; i < TN; i++) {
                ull a2 = pack2(As[r0 + i][kk]);
                ffma2(acc[i][0], a2, v2a);
                ffma2(acc[i][1], a2, v2b);
            }
        }
        __syncthreads();
    }

    float* ob = g_ow + off;
#pragma unroll
    for (int i = 0; i < TN; i++) {
        size_t rb = ((size_t)(b * n + n0 + r0 + i)) * d + e0;
        *(float2*)(ob + rb + 2 * tx)      = *reinterpret_cast<float2*>(&acc[i][0]);
        *(float2*)(ob + rb + 2 * tx + 32) = *reinterpret_cast<float2*>(&acc[i][1]);
    }
}

// ============ WMMA AV (scales 2,3): fp16 2-prod, 3 CTAs/SM ============
// smem: AH 0 (17408), AL 17408 (17408), VH 34816 (34816). total 69632.
__global__ __launch_bounds__(128, 3)
void av_h_kernel(int n, int d, long long offb_ll, long long off32_ll)
{
    extern __shared__ __align__(16) char smem[];
    u32 sb = smem_u32(smem);
    const u32 AH = 0, AL = 17408, VH = 34816;
    size_t offb = (size_t)offb_ll, off32 = (size_t)off32_ll;
    int b = blockIdx.z, n0 = blockIdx.y * 64, e0 = blockIdx.x * 128;
    int tid = threadIdx.x, wid = tid >> 5;
    int px0 = (wid & 1) * 32, oc0 = (wid >> 1) * 64;

    FragC acc[2][4];
#pragma unroll
    for (int i = 0; i < 2; i++)
#pragma unroll
        for (int j = 0; j < 4; j++) wmma::fill_fragment(acc[i][j], 0.f);

    for (int m0 = 0; m0 < n; m0 += 128) {
        for (int idx = tid; idx < 1024; idx += 128) {
            int r = idx >> 4, k8 = (idx & 15) << 3;
            u32 dd = (u32)(r * 136 + k8) * 2;
            size_t ao = ((size_t)(b * n + n0 + r)) * n + m0 + k8;
            cpa16(sb + AH + dd, g_ath + ao);
            cpa16(sb + AL + dd, g_atl + ao);
        }
        for (int idx = tid; idx < 2048; idx += 128) {
            int r = idx >> 4, k8 = (idx & 15) << 3;
            size_t vo = offb + ((size_t)(b * n + m0 + r)) * d + e0 + k8;
            cpa16(sb + VH + (u32)(r * 136 + k8) * 2, g_vh + vo);
        }
        CP_COMMIT(); CP_WAIT(0);
        __syncthreads();
        mma2<true, HFragBr>((const __half*)(smem + AH) + px0 * 136,
                            (const __half*)(smem + AL) + px0 * 136,
                            (const __half*)(smem + VH) + oc0, acc);
        __syncthreads();
    }

#pragma unroll
    for (int i = 0; i < 2; i++)
#pragma unroll
        for (int j = 0; j < 4; j++)
            wmma::store_matrix_sync(
                g_ow + off32 + ((size_t)(b * n + n0 + px0 + 16 * i)) * d + e0 + oc0 + 16 * j,
                acc[i][j], d, wmma::mem_row_major);
}

// ============ unpack windowed -> channel-last fp16 hi/lo ============
__global__ __launch_bounds__(256)
void unpack2_kernel()
{
    __shared__ float sbm[64][130];
    int y = blockIdx.x, img = blockIdx.y, tid = threadIdx.x;
    int b = img >> 3, t = img & 7;
    for (int ch = 0; ch < 2; ch++) {
        for (int idx = tid; idx < 64 * 128; idx += 256) {
            int cl = idx >> 7, xp = idx & 127;
            int c = ch * 64 + cl;
            int s = c >> 5, lph = 7 - s;
            int phm = (1 << lph) - 1;
            int n_s = 8 << (2 * s), d_s = 524288 >> (2 * s);
            int oy = y >> lph, py = y & phm;
            int ox = xp >> lph, pxm = xp & phm;
            int tok = ((((t << s) + oy) << s) + ox);
            int e = ((((c & 31) << lph) + py) << lph) + pxm;
            sbm[cl][xp] = g_ow[(size_t)s * 8388608 + ((size_t)(b * n_s + tok)) * d_s + e];
        }
        __syncthreads();
        for (int idx = tid; idx < 64 * 128; idx += 256) {
            int px = idx >> 6, cl = idx & 63;
            __half h, l;
            hsplit(sbm[cl][px], h, l);
            size_t o = (((size_t)img * 128 + y) * 128 + px) * 128 + ch * 64 + cl;
            g_ah[o] = h; g_al[o] = l;
        }
        __syncthreads();
    }
}

// ============ conv3x3 v6: fp16 2-prod, N=64 split, 2 CTAs/SM ============
// smem: AH 0 (35360), AL 35360 (35360), BH 70720 (17408). Cs overlays AH.
__global__ __launch_bounds__(128, 2)
void conv3_v6_kernel(const float* __restrict__ bias, float* __restrict__ out)
{
    extern __shared__ __align__(16) char smem[];
    u32 sb = smem_u32(smem);
    const u32 AH = 0, AL = 35360, BH = 70720;

    int bx = blockIdx.x, img = blockIdx.y;
    int y = bx >> 1, oh = bx & 1;
    int tid = threadIdx.x, wid = tid >> 5;
    int px0 = wid * 32;

    FragC acc[2][4];
#pragma unroll
    for (int i = 0; i < 2; i++)
#pragma unroll
        for (int j = 0; j < 4; j++) wmma::fill_fragment(acc[i][j], 0.f);

    for (int tp = 0; tp < 9; tp++) {
        int ky = tp / 3, kx = tp - ky * 3;
        __syncthreads();
        if (kx == 0) {
            int yy = y + ky - 1;
            bool yok = (yy >= 0 && yy < 128);
            size_t abase = (((size_t)img * 128 + (yok ? yy : 0)) * 128) * 128;
            for (int idx = tid; idx < 2080; idx += 128) {
                int i = idx >> 4, k8 = (idx & 15) << 3;
                int px = i - 1;
                u32 d = (u32)(i * 136 + k8) * 2;
                if (yok && px >= 0 && px < 128) {
                    size_t o = abase + (size_t)px * 128 + k8;
                    cpa16(sb + AH + d, g_ah + o);
                    cpa16(sb + AL + d, g_al + o);
                } else {
                    uint4 zz = make_uint4(0, 0, 0, 0);
                    *(uint4*)(smem + AH + d) = zz;
                    *(uint4*)(smem + AL + d) = zz;
                }
            }
        }
        const __half* wh = g_w3h + (size_t)tp * 16384 + oh * 8192;
        for (int idx = tid; idx < 1024; idx += 128) {
            int row = idx >> 4, k8 = (idx & 15) << 3;
            cpa16(sb + BH + (u32)(row * 136 + k8) * 2, wh + row * 128 + k8);
        }
        CP_COMMIT(); CP_WAIT(0);
        __syncthreads();

        mma2<false, HFragB>((const __half*)(smem + AH) + (px0 + kx) * 136,
                            (const __half*)(smem + AL) + (px0 + kx) * 136,
                            (const __half*)(smem + BH), acc);
    }
    __syncthreads();

    float* Cs = (float*)(smem + AH);    // [128][72] = 36864 B (fits A region)
#pragma unroll
    for (int i = 0; i < 2; i++)
#pragma unroll
        for (int j = 0; j < 4; j++)
            wmma::store_matrix_sync(&Cs[(px0 + 16 * i) * 72 + 16 * j],
                                    acc[i][j], 72, wmma::mem_row_major);
    __syncthreads();

    for (int idx = tid; idx < 8192; idx += 128) {
        int oc = idx >> 7, px = idx & 127;
        float v = Cs[px * 72 + oc] + bias[oh * 64 + oc];
        out[((size_t)img * 128 + oh * 64 + oc) * HWs + (size_t)y * 128 + px] =
            fmaxf(v, 0.f);
    }
}

// ============ launch ============
extern "C" void kernel_launch(void* const* d_in, const int* in_sizes, int n_in,
                              void* d_out, int out_size)
{
    const float* x  = (const float*)d_in[0];
    const float* wq = (const float*)d_in[1];
    const float* bq = (const float*)d_in[2];
    const float* wk = (const float*)d_in[3];
    const float* bk = (const float*)d_in[4];
    const float* wv = (const float*)d_in[5];
    const float* bv = (const float*)d_in[6];
    const float* wo = (const float*)d_in[7];
    const float* bo = (const float*)d_in[8];
    float* out = (float*)d_out;

    const int smem1 = 87040, smem3 = 88128, smemW = 69632;
    cudaFuncSetAttribute(conv1_v8_kernel,
                         cudaFuncAttributeMaxDynamicSharedMemorySize, smem1);
    cudaFuncSetAttribute(conv3_v6_kernel,
                         cudaFuncAttributeMaxDynamicSharedMemorySize, smem3);
    cudaFuncSetAttribute(scores_h_kernel,
                         cudaFuncAttributeMaxDynamicSharedMemorySize, smemW);
    cudaFuncSetAttribute(av_h_kernel,
                         cudaFuncAttributeMaxDynamicSharedMemorySize, smemW);

    dim3 blk(16, 16);

    prep_w3_kernel<<<(9 * 128 * 128 + 255) / 256, 256>>>(wo);
    prep_w1_kernel<<<(3 * 16384 + 255) / 256, 256>>>(wq, wk, wv);
    prep_x_kernel<<<dim3(Hd, BT), 256>>>(x);
    conv1_v8_kernel<<<dim3(768, BT), 128, smem1>>>(bq, bk, bv);

    // scale 0: n=8, d=524288 (scalar fp32)
    {
        float isd = 1.0f / sqrtf(524288.f);
        scores0_kernel<<<dim3(1024, NBm), 256>>>();
        softmax_kernel<<<dim3(8, NBm), 256>>>(8, 1024, isd, 0);
        av2_kernel<8, 1><<<dim3(524288 / 64, 1, NBm), blk>>>(8, 524288, 0LL);
    }
    // scale 1: n=32, d=131072 (scalar fp32)
    {
        float isd = 1.0f / sqrtf(131072.f);
        scores2_kernel<32, 2><<<dim3(1, NBm, 256), blk>>>(32, 131072, 8388608LL, 1, 512);
        softmax_kernel<<<dim3(32, NBm), 256>>>(32, 256, isd, 0);
        av2_kernel<32, 2><<<dim3(131072 / 64, 1, NBm), blk>>>(32, 131072, 8388608LL);
    }
    // scale 2: n=128, d=32768 (fp16 WMMA)
    {
        float isd = 1.0f / sqrtf(32768.f);
        scores_h_kernel<<<dim3(2, NBm, 128), 128, smemW>>>(128, 32768, 0LL, 1, 256);
        softmax_kernel<<<dim3(128, NBm), 256>>>(128, 128, isd, 1);
        av_h_kernel<<<dim3(256, 2, NBm), 128, smemW>>>(128, 32768, 0LL, 2LL * 8388608);
    }
    // scale 3: n=512, d=8192 (fp16 WMMA)
    {
        float isd = 1.0f / sqrtf(8192.f);
        scores_h_kernel<<<dim3(32, NBm, 8), 128, smemW>>>(512, 8192, 8388608LL, 4, 1024);
        softmax_kernel<<<dim3(512, NBm), 256>>>(512, 8, isd, 1);
        av_h_kernel<<<dim3(64, 8, NBm), 128, smemW>>>(512, 8192, 8388608LL, 3LL * 8388608);
    }

    unpack2_kernel<<<dim3(Hd, BT), 256>>>();
    conv3_v6_kernel<<<dim3(256, BT), 128, smem3>>>(bo, out);

    (void)in_sizes; (void)n_in; (void)out_size;
}